// round 12
// baseline (speedup 1.0000x reference)
#include <cuda_runtime.h>
#include <cuda_fp16.h>

#define EPS_W  1e-8f
#define EPS_LN 1e-5f
// final rows: etrc(64*4=256) + fc(256) + sc(512) + oftt(128*64=8192)
#define NROWS  9216
#define DOUT   256

// Fused, column-permuted, ROW-CENTERED fp16 table.
// Row r, physical half index 8*l+c (l in [0,32), c in [0,8)):
//   c<4  -> logical output col 4*l+c ; c>=4 -> col 128 + 4*l + (c-4)
// Every row has its mean subtracted at build time, so the gathered sum z'
// equals z - mean(z) exactly -> LayerNorm mean reduction is FREE in k_main.
// Row blocks: [0,256)=etrc (bias folded), [256,512)=fc, [512,1024)=sc,
//             [1024,9216)=oftt (of*64+tt)
__device__ __align__(16) __half g_Ph[NROWS * DOUT];
// quantized weights (w_eff = clip(rint(W/scale))*scale), computed ONCE
__device__ __align__(16) float g_Wq[256 * 96];
// fp32 permuted scratch rows: et[0,64) rc[64,68) fc[68,324) sc[324,836)
//                             of[836,964) tt[964,1028)
__device__ __align__(16) float g_Pf[1028 * DOUT];
__device__ int g_stride;   // 2 if indices are int64 (read low words), 1 if int32

// ---------------------------------------------------------------------------
// Block 0: detect index dtype. Block 1: scale = mean|W| then quantize W once.
__global__ void k_pre(const int* __restrict__ ev, const float* __restrict__ W) {
    if (blockIdx.x == 0) {
        __shared__ int any;
        if (threadIdx.x == 0) any = 0;
        __syncthreads();
        int nz = 0;
        for (int i = threadIdx.x; i < 256; i += blockDim.x)
            if (ev[2 * i + 1] != 0) nz = 1;
        if (nz) atomicOr(&any, 1);
        __syncthreads();
        if (threadIdx.x == 0) g_stride = any ? 1 : 2;
    } else {
        __shared__ float red[32];
        __shared__ float s_scale;
        int tid = threadIdx.x;  // 1024 threads
        float s = 0.f;
        for (int i = tid; i < 24576; i += 1024) s += fabsf(W[i]);
        #pragma unroll
        for (int o = 16; o > 0; o >>= 1) s += __shfl_xor_sync(~0u, s, o);
        if ((tid & 31) == 0) red[tid >> 5] = s;
        __syncthreads();
        if (tid < 32) {
            float v = red[tid];
            #pragma unroll
            for (int o = 16; o > 0; o >>= 1) v += __shfl_xor_sync(~0u, v, o);
            if (tid == 0) s_scale = v / 24576.0f;
        }
        __syncthreads();
        float scale = s_scale;
        float inv = 1.0f / (scale + EPS_W);
        for (int i = tid; i < 24576; i += 1024) {
            float q = rintf(W[i] * inv);          // round-half-to-even == jnp.round
            q = fminf(1.0f, fmaxf(-1.0f, q));
            g_Wq[i] = q * scale;
        }
    }
}

// ---------------------------------------------------------------------------
__device__ __forceinline__ int permcol(int o) {
    return (o < 128) ? (((o >> 2) << 3) + (o & 3))
                     : ((((o - 128) >> 2) << 3) + 4 + ((o - 128) & 3));
}

__device__ __forceinline__ float qdotq(const float* __restrict__ E, int v,
                                       int o, int t, float acc) {
    #pragma unroll
    for (int k = 0; k < 16; k++)
        acc = fmaf(E[v * 16 + k], g_Wq[o * 96 + t * 16 + k], acc);
    return acc;
}

// Per-table projection rows (1028 blocks, 256 threads = output channels),
// all into fp32 permuted scratch.
__global__ void k_small(const float* __restrict__ bias,
                        const float* __restrict__ E_et, const float* __restrict__ E_fc,
                        const float* __restrict__ E_sc, const float* __restrict__ E_of,
                        const float* __restrict__ E_tt, const float* __restrict__ E_rc) {
    int r = blockIdx.x, o = threadIdx.x;
    int c = permcol(o);
    float v;
    if (r < 64)        v = qdotq(E_et, r,        o, 0, 0.0f);       // et
    else if (r < 68)   v = qdotq(E_rc, r - 64,   o, 5, bias[o]);    // rc (+bias)
    else if (r < 324)  v = qdotq(E_fc, r - 68,   o, 1, 0.0f);       // fc
    else if (r < 836)  v = qdotq(E_sc, r - 324,  o, 2, 0.0f);       // sc
    else if (r < 964)  v = qdotq(E_of, r - 836,  o, 3, 0.0f);       // of
    else               v = qdotq(E_tt, r - 964,  o, 4, 0.0f);       // tt
    g_Pf[r * DOUT + c] = v;
}

// ---------------------------------------------------------------------------
// Compose all 9216 final rows: pair-sum (etrc/oftt) or copy (fc/sc),
// then CENTER (subtract row mean) and pack fp16. One warp per row.
__global__ void k_fuse() {
    int row  = blockIdx.x * 8 + (threadIdx.x >> 5);   // 0..9215
    int lane = threadIdx.x & 31;
    const float4* A; const float4* B;
    if (row < 256) {                 // etrc = et + rc
        A = (const float4*)(g_Pf + (row >> 2) * DOUT);
        B = (const float4*)(g_Pf + (64 + (row & 3)) * DOUT);
    } else if (row < 512) {          // fc
        A = (const float4*)(g_Pf + (68 + row - 256) * DOUT);
        B = nullptr;
    } else if (row < 1024) {         // sc
        A = (const float4*)(g_Pf + (324 + row - 512) * DOUT);
        B = nullptr;
    } else {                         // oftt = of + tt
        int rr = row - 1024;
        A = (const float4*)(g_Pf + (836 + (rr >> 6)) * DOUT);
        B = (const float4*)(g_Pf + (964 + (rr & 63)) * DOUT);
    }
    float4 v0 = A[lane], v1 = A[lane + 32];
    if (B) {
        float4 b0 = B[lane], b1 = B[lane + 32];
        v0.x += b0.x; v0.y += b0.y; v0.z += b0.z; v0.w += b0.w;
        v1.x += b1.x; v1.y += b1.y; v1.z += b1.z; v1.w += b1.w;
    }
    float s = v0.x + v0.y + v0.z + v0.w + v1.x + v1.y + v1.z + v1.w;
    #pragma unroll
    for (int o = 16; o > 0; o >>= 1) s += __shfl_xor_sync(~0u, s, o);
    float mu = s * (1.0f / 256.0f);
    v0.x -= mu; v0.y -= mu; v0.z -= mu; v0.w -= mu;
    v1.x -= mu; v1.y -= mu; v1.z -= mu; v1.w -= mu;
    __half2 a0 = __floats2half2_rn(v0.x, v0.y);
    __half2 a1 = __floats2half2_rn(v0.z, v0.w);
    __half2 a2 = __floats2half2_rn(v1.x, v1.y);
    __half2 a3 = __floats2half2_rn(v1.z, v1.w);
    uint2* dst = (uint2*)(g_Ph + row * DOUT);
    dst[lane]      = make_uint2(*(unsigned*)&a0, *(unsigned*)&a1);
    dst[lane + 32] = make_uint2(*(unsigned*)&a2, *(unsigned*)&a3);
}

// ---------------------------------------------------------------------------
__device__ __forceinline__ __half2 h2(unsigned u) { return *reinterpret_cast<__half2*>(&u); }

// Main: one warp per token, 32-token tiles; lane owns cols [4l,4l+4) and
// [128+4l, +4). 4 uint4 gathers/token, fp16 accumulation.
// Table rows are pre-centered -> z is already mean-subtracted; only the
// sum-of-squares warp reduction remains for LayerNorm.
__global__ void __launch_bounds__(256) k_main(
    const int* __restrict__ i0, const int* __restrict__ i1,
    const int* __restrict__ i2, const int* __restrict__ i3,
    const int* __restrict__ i4, const int* __restrict__ i5,
    const float* __restrict__ gamma, const float* __restrict__ beta,
    float* __restrict__ out, int ntok)
{
    const uint4* __restrict__ Pu = (const uint4*)g_Ph;   // 32 uint4 per row
    int lane  = threadIdx.x & 31;
    int warp  = blockIdx.x * (blockDim.x >> 5) + (threadIdx.x >> 5);
    int nwarp = gridDim.x * (blockDim.x >> 5);
    int stride = g_stride;

    float4 gg0 = ((const float4*)gamma)[lane];
    float4 gg1 = ((const float4*)gamma)[lane + 32];
    float4 bb0 = ((const float4*)beta )[lane];
    float4 bb1 = ((const float4*)beta )[lane + 32];

    int ntiles = (ntok + 31) >> 5;
    for (int tile = warp; tile < ntiles; tile += nwarp) {
        int t0 = tile << 5;
        int nt = min(32, ntok - t0);

        // Coalesced per-lane index loads (lane j -> token t0+j), packed:
        //   p = r0 | r1<<8 | r2<<16   (r0<256, r1<256, r2<512 -> 25 bits)
        //   q = r3                    (oftt row < 8192)
        int p = 0, q = 0;
        if (lane < nt) {
            size_t ti = (size_t)(t0 + lane) * (size_t)stride;
            int r0 = (i0[ti] << 2) + i5[ti];      // etrc = et*4 + rc
            int r1 = i1[ti];                      // fc
            int r2 = i2[ti];                      // sc
            q      = (i3[ti] << 6) + i4[ti];      // oftt = of*64 + tt
            p = r0 | (r1 << 8) | (r2 << 16);
        }

        for (int j = 0; j < nt; j++) {
            int pk = __shfl_sync(~0u, p, j);
            int qk = __shfl_sync(~0u, q, j);
            int b0 = ((pk & 255)          ) * 32 + lane;
            int b1 = (((pk >> 8) & 255) + 256) * 32 + lane;
            int b2 = ((pk >> 16) + 512) * 32 + lane;
            int b3 = (qk + 1024) * 32 + lane;

            // 4 gathers (one uint4 each), issued up front for MLP.
            uint4 q0 = Pu[b0];
            uint4 q1 = Pu[b1];
            uint4 q2 = Pu[b2];
            uint4 q3 = Pu[b3];

            // fp16 accumulation: 4 half2 slots x 3 adds
            __half2 h0 = __hadd2(h2(q0.x), h2(q1.x));
            __half2 h1 = __hadd2(h2(q0.y), h2(q1.y));
            __half2 h2v= __hadd2(h2(q0.z), h2(q1.z));
            __half2 h3 = __hadd2(h2(q0.w), h2(q1.w));
            h0 = __hadd2(h0, h2(q2.x));  h1 = __hadd2(h1, h2(q2.y));
            h2v= __hadd2(h2v,h2(q2.z));  h3 = __hadd2(h3, h2(q2.w));
            h0 = __hadd2(h0, h2(q3.x));  h1 = __hadd2(h1, h2(q3.y));
            h2v= __hadd2(h2v,h2(q3.z));  h3 = __hadd2(h3, h2(q3.w));

            // convert once to fp32 (z is already centered)
            float2 f0 = __half22float2(h0);
            float2 f1 = __half22float2(h1);
            float2 f2 = __half22float2(h2v);
            float2 f3 = __half22float2(h3);
            float4 z0 = make_float4(f0.x, f0.y, f1.x, f1.y);   // cols 4l..4l+3
            float4 z1 = make_float4(f2.x, f2.y, f3.x, f3.y);   // cols 128+4l..

            float sq = z0.x*z0.x + z0.y*z0.y + z0.z*z0.z + z0.w*z0.w
                     + z1.x*z1.x + z1.y*z1.y + z1.z*z1.z + z1.w*z1.w;
            #pragma unroll
            for (int o = 16; o > 0; o >>= 1)
                sq += __shfl_xor_sync(~0u, sq, o);

            float rstd = rsqrtf(sq * (1.0f / 256.0f) + EPS_LN);

            float4* op = (float4*)(out + (size_t)(t0 + j) * DOUT);
            float4 o0, o1;
            o0.x = z0.x * rstd * gg0.x + bb0.x;
            o0.y = z0.y * rstd * gg0.y + bb0.y;
            o0.z = z0.z * rstd * gg0.z + bb0.z;
            o0.w = z0.w * rstd * gg0.w + bb0.w;
            o1.x = z1.x * rstd * gg1.x + bb1.x;
            o1.y = z1.y * rstd * gg1.y + bb1.y;
            o1.z = z1.z * rstd * gg1.z + bb1.z;
            o1.w = z1.w * rstd * gg1.w + bb1.w;
            __stcs(op + lane,      o0);   // streaming store: keep L2 for the table
            __stcs(op + 32 + lane, o1);
        }
    }
}

// ---------------------------------------------------------------------------
extern "C" void kernel_launch(void* const* d_in, const int* in_sizes, int n_in,
                              void* d_out, int out_size) {
    // Inputs (metadata order):
    // 0..5 : event_type, fault_class, syscall_class, opcode_family,
    //        transition_type, result_class        [B,S] integer
    // 6..11: E_et[64,16] E_fc[256,16] E_sc[512,16] E_of[128,16] E_tt[64,16] E_rc[4,16]
    // 12: W[256,96]  13: b[256]  14: gamma[256]  15: beta[256]
    int ntok = in_sizes[0];

    k_pre<<<2, 1024>>>((const int*)d_in[0], (const float*)d_in[12]);
    k_small<<<1028, 256>>>((const float*)d_in[13],
                           (const float*)d_in[6], (const float*)d_in[7],
                           (const float*)d_in[8], (const float*)d_in[9],
                           (const float*)d_in[10], (const float*)d_in[11]);
    k_fuse<<<1152, 256>>>();
    k_main<<<2048, 256>>>((const int*)d_in[0], (const int*)d_in[1],
                          (const int*)d_in[2], (const int*)d_in[3],
                          (const int*)d_in[4], (const int*)d_in[5],
                          (const float*)d_in[14], (const float*)d_in[15],
                          (float*)d_out, ntok);
}

// round 13
// speedup vs baseline: 1.0298x; 1.0298x over previous
#include <cuda_runtime.h>
#include <cuda_fp16.h>

#define EPS_W  1e-8f
#define EPS_LN 1e-5f
// final rows: etrc(64*4=256) + fc(256) + sc(512) + oftt(128*64=8192)
#define NROWS  9216
#define DOUT   256

// Fused, column-permuted, ROW-CENTERED fp16 table.
// Row r, physical half index 8*l+c (l in [0,32), c in [0,8)):
//   c<4  -> logical output col 4*l+c ; c>=4 -> col 128 + 4*l + (c-4)
// Every row has its mean subtracted at build time, so the gathered sum z'
// equals z - mean(z) exactly -> LayerNorm mean reduction is FREE in k_main.
// Row blocks: [0,256)=etrc (bias folded), [256,512)=fc, [512,1024)=sc,
//             [1024,9216)=oftt (of*64+tt)
__device__ __align__(16) __half g_Ph[NROWS * DOUT];
// quantized weights (w_eff = clip(rint(W/scale))*scale), computed ONCE
__device__ __align__(16) float g_Wq[256 * 96];
// fp32 permuted scratch rows: et[0,64) rc[64,68) fc[68,324) sc[324,836)
//                             of[836,964) tt[964,1028)
__device__ __align__(16) float g_Pf[1028 * DOUT];
__device__ int g_stride;   // 2 if indices are int64 (read low words), 1 if int32

// ---------------------------------------------------------------------------
// Block 0: detect index dtype. Block 1: scale = mean|W| then quantize W once.
__global__ void k_pre(const int* __restrict__ ev, const float* __restrict__ W) {
    if (blockIdx.x == 0) {
        __shared__ int any;
        if (threadIdx.x == 0) any = 0;
        __syncthreads();
        int nz = 0;
        for (int i = threadIdx.x; i < 256; i += blockDim.x)
            if (ev[2 * i + 1] != 0) nz = 1;
        if (nz) atomicOr(&any, 1);
        __syncthreads();
        if (threadIdx.x == 0) g_stride = any ? 1 : 2;
    } else {
        __shared__ float red[32];
        __shared__ float s_scale;
        int tid = threadIdx.x;  // 1024 threads
        float s = 0.f;
        for (int i = tid; i < 24576; i += 1024) s += fabsf(W[i]);
        #pragma unroll
        for (int o = 16; o > 0; o >>= 1) s += __shfl_xor_sync(~0u, s, o);
        if ((tid & 31) == 0) red[tid >> 5] = s;
        __syncthreads();
        if (tid < 32) {
            float v = red[tid];
            #pragma unroll
            for (int o = 16; o > 0; o >>= 1) v += __shfl_xor_sync(~0u, v, o);
            if (tid == 0) s_scale = v / 24576.0f;
        }
        __syncthreads();
        float scale = s_scale;
        float inv = 1.0f / (scale + EPS_W);
        for (int i = tid; i < 24576; i += 1024) {
            float q = rintf(W[i] * inv);          // round-half-to-even == jnp.round
            q = fminf(1.0f, fmaxf(-1.0f, q));
            g_Wq[i] = q * scale;
        }
    }
}

// ---------------------------------------------------------------------------
__device__ __forceinline__ int permcol(int o) {
    return (o < 128) ? (((o >> 2) << 3) + (o & 3))
                     : ((((o - 128) >> 2) << 3) + 4 + ((o - 128) & 3));
}

__device__ __forceinline__ float qdotq(const float* __restrict__ E, int v,
                                       int o, int t, float acc) {
    #pragma unroll
    for (int k = 0; k < 16; k++)
        acc = fmaf(E[v * 16 + k], g_Wq[o * 96 + t * 16 + k], acc);
    return acc;
}

// Per-table projection rows (1028 blocks, 256 threads = output channels),
// all into fp32 permuted scratch.
__global__ void k_small(const float* __restrict__ bias,
                        const float* __restrict__ E_et, const float* __restrict__ E_fc,
                        const float* __restrict__ E_sc, const float* __restrict__ E_of,
                        const float* __restrict__ E_tt, const float* __restrict__ E_rc) {
    int r = blockIdx.x, o = threadIdx.x;
    int c = permcol(o);
    float v;
    if (r < 64)        v = qdotq(E_et, r,        o, 0, 0.0f);       // et
    else if (r < 68)   v = qdotq(E_rc, r - 64,   o, 5, bias[o]);    // rc (+bias)
    else if (r < 324)  v = qdotq(E_fc, r - 68,   o, 1, 0.0f);       // fc
    else if (r < 836)  v = qdotq(E_sc, r - 324,  o, 2, 0.0f);       // sc
    else if (r < 964)  v = qdotq(E_of, r - 836,  o, 3, 0.0f);       // of
    else               v = qdotq(E_tt, r - 964,  o, 4, 0.0f);       // tt
    g_Pf[r * DOUT + c] = v;
}

// ---------------------------------------------------------------------------
// Compose all 9216 final rows: pair-sum (etrc/oftt) or copy (fc/sc),
// then CENTER (subtract row mean) and pack fp16. One warp per row.
__global__ void k_fuse() {
    int row  = blockIdx.x * 8 + (threadIdx.x >> 5);   // 0..9215
    int lane = threadIdx.x & 31;
    const float4* A; const float4* B;
    if (row < 256) {                 // etrc = et + rc
        A = (const float4*)(g_Pf + (row >> 2) * DOUT);
        B = (const float4*)(g_Pf + (64 + (row & 3)) * DOUT);
    } else if (row < 512) {          // fc
        A = (const float4*)(g_Pf + (68 + row - 256) * DOUT);
        B = nullptr;
    } else if (row < 1024) {         // sc
        A = (const float4*)(g_Pf + (324 + row - 512) * DOUT);
        B = nullptr;
    } else {                         // oftt = of + tt
        int rr = row - 1024;
        A = (const float4*)(g_Pf + (836 + (rr >> 6)) * DOUT);
        B = (const float4*)(g_Pf + (964 + (rr & 63)) * DOUT);
    }
    float4 v0 = A[lane], v1 = A[lane + 32];
    if (B) {
        float4 b0 = B[lane], b1 = B[lane + 32];
        v0.x += b0.x; v0.y += b0.y; v0.z += b0.z; v0.w += b0.w;
        v1.x += b1.x; v1.y += b1.y; v1.z += b1.z; v1.w += b1.w;
    }
    float s = v0.x + v0.y + v0.z + v0.w + v1.x + v1.y + v1.z + v1.w;
    #pragma unroll
    for (int o = 16; o > 0; o >>= 1) s += __shfl_xor_sync(~0u, s, o);
    float mu = s * (1.0f / 256.0f);
    v0.x -= mu; v0.y -= mu; v0.z -= mu; v0.w -= mu;
    v1.x -= mu; v1.y -= mu; v1.z -= mu; v1.w -= mu;
    __half2 a0 = __floats2half2_rn(v0.x, v0.y);
    __half2 a1 = __floats2half2_rn(v0.z, v0.w);
    __half2 a2 = __floats2half2_rn(v1.x, v1.y);
    __half2 a3 = __floats2half2_rn(v1.z, v1.w);
    uint2* dst = (uint2*)(g_Ph + row * DOUT);
    dst[lane]      = make_uint2(*(unsigned*)&a0, *(unsigned*)&a1);
    dst[lane + 32] = make_uint2(*(unsigned*)&a2, *(unsigned*)&a3);
}

// ---------------------------------------------------------------------------
__device__ __forceinline__ __half2 h2(unsigned u) { return *reinterpret_cast<__half2*>(&u); }

// Accumulate 4 table rows (uint4 each) -> centered fp32 z0/z1 for one token.
__device__ __forceinline__ void acc_token(uint4 q0, uint4 q1, uint4 q2, uint4 q3,
                                          float4& z0, float4& z1) {
    __half2 h0 = __hadd2(h2(q0.x), h2(q1.x));
    __half2 h1 = __hadd2(h2(q0.y), h2(q1.y));
    __half2 h2v= __hadd2(h2(q0.z), h2(q1.z));
    __half2 h3 = __hadd2(h2(q0.w), h2(q1.w));
    h0 = __hadd2(h0, h2(q2.x));  h1 = __hadd2(h1, h2(q2.y));
    h2v= __hadd2(h2v,h2(q2.z));  h3 = __hadd2(h3, h2(q2.w));
    h0 = __hadd2(h0, h2(q3.x));  h1 = __hadd2(h1, h2(q3.y));
    h2v= __hadd2(h2v,h2(q3.z));  h3 = __hadd2(h3, h2(q3.w));
    float2 f0 = __half22float2(h0);
    float2 f1 = __half22float2(h1);
    float2 f2 = __half22float2(h2v);
    float2 f3 = __half22float2(h3);
    z0 = make_float4(f0.x, f0.y, f1.x, f1.y);
    z1 = make_float4(f2.x, f2.y, f3.x, f3.y);
}

// Main: one warp per 32-token tile, TWO tokens per inner iteration so 8
// independent gathers are in flight (latency hiding). Lane owns cols
// [4l,4l+4) and [128+4l,+4). Table pre-centered -> only sum-of-squares
// reduction remains for LayerNorm.
__global__ void __launch_bounds__(256) k_main(
    const int* __restrict__ i0, const int* __restrict__ i1,
    const int* __restrict__ i2, const int* __restrict__ i3,
    const int* __restrict__ i4, const int* __restrict__ i5,
    const float* __restrict__ gamma, const float* __restrict__ beta,
    float* __restrict__ out, int ntok)
{
    const uint4* __restrict__ Pu = (const uint4*)g_Ph;   // 32 uint4 per row
    int lane  = threadIdx.x & 31;
    int warp  = blockIdx.x * (blockDim.x >> 5) + (threadIdx.x >> 5);
    int nwarp = gridDim.x * (blockDim.x >> 5);
    int stride = g_stride;

    float4 gg0 = ((const float4*)gamma)[lane];
    float4 gg1 = ((const float4*)gamma)[lane + 32];
    float4 bb0 = ((const float4*)beta )[lane];
    float4 bb1 = ((const float4*)beta )[lane + 32];

    int ntiles = (ntok + 31) >> 5;
    for (int tile = warp; tile < ntiles; tile += nwarp) {
        int t0 = tile << 5;
        int nt = min(32, ntok - t0);

        // Coalesced per-lane index loads (lane j -> token t0+j), packed:
        //   p = r0 | r1<<8 | r2<<16   (r0<256, r1<256, r2<512 -> 25 bits)
        //   q = r3                    (oftt row < 8192)
        int p = 0, q = 0;
        if (lane < nt) {
            size_t ti = (size_t)(t0 + lane) * (size_t)stride;
            int r0 = (i0[ti] << 2) + i5[ti];      // etrc = et*4 + rc
            int r1 = i1[ti];                      // fc
            int r2 = i2[ti];                      // sc
            q      = (i3[ti] << 6) + i4[ti];      // oftt = of*64 + tt
            p = r0 | (r1 << 8) | (r2 << 16);
        }

        int j = 0;
        for (; j + 2 <= nt; j += 2) {
            int pkA = __shfl_sync(~0u, p, j);
            int qkA = __shfl_sync(~0u, q, j);
            int pkB = __shfl_sync(~0u, p, j + 1);
            int qkB = __shfl_sync(~0u, q, j + 1);

            int a0 = ((pkA & 255)             ) * 32 + lane;
            int a1 = (((pkA >> 8) & 255) + 256) * 32 + lane;
            int a2 = ((pkA >> 16) + 512) * 32 + lane;
            int a3 = (qkA + 1024) * 32 + lane;
            int b0 = ((pkB & 255)             ) * 32 + lane;
            int b1 = (((pkB >> 8) & 255) + 256) * 32 + lane;
            int b2 = ((pkB >> 16) + 512) * 32 + lane;
            int b3 = (qkB + 1024) * 32 + lane;

            // 8 independent gathers in flight.
            uint4 qa0 = Pu[a0];
            uint4 qa1 = Pu[a1];
            uint4 qa2 = Pu[a2];
            uint4 qa3 = Pu[a3];
            uint4 qb0 = Pu[b0];
            uint4 qb1 = Pu[b1];
            uint4 qb2 = Pu[b2];
            uint4 qb3 = Pu[b3];

            float4 zA0, zA1, zB0, zB1;
            acc_token(qa0, qa1, qa2, qa3, zA0, zA1);
            acc_token(qb0, qb1, qb2, qb3, zB0, zB1);

            float sqA = zA0.x*zA0.x + zA0.y*zA0.y + zA0.z*zA0.z + zA0.w*zA0.w
                      + zA1.x*zA1.x + zA1.y*zA1.y + zA1.z*zA1.z + zA1.w*zA1.w;
            float sqB = zB0.x*zB0.x + zB0.y*zB0.y + zB0.z*zB0.z + zB0.w*zB0.w
                      + zB1.x*zB1.x + zB1.y*zB1.y + zB1.z*zB1.z + zB1.w*zB1.w;
            #pragma unroll
            for (int o = 16; o > 0; o >>= 1) {
                sqA += __shfl_xor_sync(~0u, sqA, o);
                sqB += __shfl_xor_sync(~0u, sqB, o);
            }
            float rstdA = rsqrtf(sqA * (1.0f / 256.0f) + EPS_LN);
            float rstdB = rsqrtf(sqB * (1.0f / 256.0f) + EPS_LN);

            float4* opA = (float4*)(out + (size_t)(t0 + j) * DOUT);
            float4* opB = (float4*)(out + (size_t)(t0 + j + 1) * DOUT);
            float4 o0, o1;
            o0.x = zA0.x * rstdA * gg0.x + bb0.x;
            o0.y = zA0.y * rstdA * gg0.y + bb0.y;
            o0.z = zA0.z * rstdA * gg0.z + bb0.z;
            o0.w = zA0.w * rstdA * gg0.w + bb0.w;
            o1.x = zA1.x * rstdA * gg1.x + bb1.x;
            o1.y = zA1.y * rstdA * gg1.y + bb1.y;
            o1.z = zA1.z * rstdA * gg1.z + bb1.z;
            o1.w = zA1.w * rstdA * gg1.w + bb1.w;
            __stcs(opA + lane,      o0);
            __stcs(opA + 32 + lane, o1);
            o0.x = zB0.x * rstdB * gg0.x + bb0.x;
            o0.y = zB0.y * rstdB * gg0.y + bb0.y;
            o0.z = zB0.z * rstdB * gg0.z + bb0.z;
            o0.w = zB0.w * rstdB * gg0.w + bb0.w;
            o1.x = zB1.x * rstdB * gg1.x + bb1.x;
            o1.y = zB1.y * rstdB * gg1.y + bb1.y;
            o1.z = zB1.z * rstdB * gg1.z + bb1.z;
            o1.w = zB1.w * rstdB * gg1.w + bb1.w;
            __stcs(opB + lane,      o0);
            __stcs(opB + 32 + lane, o1);
        }
        // tail (odd nt)
        for (; j < nt; j++) {
            int pk = __shfl_sync(~0u, p, j);
            int qk = __shfl_sync(~0u, q, j);
            int a0 = ((pk & 255)             ) * 32 + lane;
            int a1 = (((pk >> 8) & 255) + 256) * 32 + lane;
            int a2 = ((pk >> 16) + 512) * 32 + lane;
            int a3 = (qk + 1024) * 32 + lane;
            uint4 q0 = Pu[a0];
            uint4 q1 = Pu[a1];
            uint4 q2 = Pu[a2];
            uint4 q3 = Pu[a3];
            float4 z0, z1;
            acc_token(q0, q1, q2, q3, z0, z1);
            float sq = z0.x*z0.x + z0.y*z0.y + z0.z*z0.z + z0.w*z0.w
                     + z1.x*z1.x + z1.y*z1.y + z1.z*z1.z + z1.w*z1.w;
            #pragma unroll
            for (int o = 16; o > 0; o >>= 1)
                sq += __shfl_xor_sync(~0u, sq, o);
            float rstd = rsqrtf(sq * (1.0f / 256.0f) + EPS_LN);
            float4* op = (float4*)(out + (size_t)(t0 + j) * DOUT);
            float4 o0, o1;
            o0.x = z0.x * rstd * gg0.x + bb0.x;
            o0.y = z0.y * rstd * gg0.y + bb0.y;
            o0.z = z0.z * rstd * gg0.z + bb0.z;
            o0.w = z0.w * rstd * gg0.w + bb0.w;
            o1.x = z1.x * rstd * gg1.x + bb1.x;
            o1.y = z1.y * rstd * gg1.y + bb1.y;
            o1.z = z1.z * rstd * gg1.z + bb1.z;
            o1.w = z1.w * rstd * gg1.w + bb1.w;
            __stcs(op + lane,      o0);
            __stcs(op + 32 + lane, o1);
        }
    }
}

// ---------------------------------------------------------------------------
extern "C" void kernel_launch(void* const* d_in, const int* in_sizes, int n_in,
                              void* d_out, int out_size) {
    // Inputs (metadata order):
    // 0..5 : event_type, fault_class, syscall_class, opcode_family,
    //        transition_type, result_class        [B,S] integer
    // 6..11: E_et[64,16] E_fc[256,16] E_sc[512,16] E_of[128,16] E_tt[64,16] E_rc[4,16]
    // 12: W[256,96]  13: b[256]  14: gamma[256]  15: beta[256]
    int ntok = in_sizes[0];

    k_pre<<<2, 1024>>>((const int*)d_in[0], (const float*)d_in[12]);
    k_small<<<1028, 256>>>((const float*)d_in[13],
                           (const float*)d_in[6], (const float*)d_in[7],
                           (const float*)d_in[8], (const float*)d_in[9],
                           (const float*)d_in[10], (const float*)d_in[11]);
    k_fuse<<<1152, 256>>>();
    k_main<<<2048, 256>>>((const int*)d_in[0], (const int*)d_in[1],
                          (const int*)d_in[2], (const int*)d_in[3],
                          (const int*)d_in[4], (const int*)d_in[5],
                          (const float*)d_in[14], (const float*)d_in[15],
                          (float*)d_out, ntok);
}